// round 6
// baseline (speedup 1.0000x reference)
#include <cuda_runtime.h>
#include <math.h>

#define N    768
#define CN   384
#define CZ   128
#define CC   16
#define H    12
#define PQ   4
#define PV   8
#define NN   (N*N)                 // 589824
#define HC   (H*CC)                // 192
#define KV_COLS (2*HC)             // 384
#define QP_COLS (H*PQ*3)           // 144
#define KVP_COLS (H*12*3)          // 432
#define CAT_DIM (H*(CZ+CC+PV*4))   // 2112
#define INFV 100000.0f
#define EPSV 1e-8f

#define ASH_STRIDE 776
// smem float offsets for k_softmax_opair
#define OP_ASH 0
#define OP_RED (12*ASH_STRIDE)               // 9312
#define OP_SMEM_FLOATS (OP_RED + 8*6*128)    // 9312 + 6144 = 15456
#define OP_SMEM_BYTES (OP_SMEM_FLOATS*4)     // 61824

// ---------------- scratch ----------------
__device__ float g_qlin  [N*HC];
__device__ float g_kvlin [N*KV_COLS];
__device__ float g_qplin [N*QP_COLS];
__device__ float g_kvplin[N*KVP_COLS];
__device__ float g_qpts  [N*H*PQ*3];
__device__ float g_kpts  [N*H*PQ*3];
__device__ float g_vpts  [N*H*PV*3];
__device__ float g_logits[H*NN];        // 28 MB: logits, then softmaxed a
__device__ float g_optg  [N*H*PV*3];
__device__ float g_cat   [N*CAT_DIM];

// ---------------- f32x2 packed-FMA helpers ----------------
__device__ __forceinline__ void fma2(unsigned long long& acc, unsigned long long a, unsigned long long b) {
    asm("fma.rn.f32x2 %0, %1, %2, %0;" : "+l"(acc) : "l"(a), "l"(b));
}
__device__ __forceinline__ unsigned long long pk2(float a, float b) {
    unsigned long long r; asm("mov.b64 %0, {%1,%2};" : "=l"(r) : "f"(a), "f"(b)); return r;
}
__device__ __forceinline__ float hsum2(unsigned long long v) {
    float x, y; asm("mov.b64 {%0,%1}, %2;" : "=f"(x), "=f"(y) : "l"(v)); return x + y;
}
__device__ __forceinline__ void unpk2(unsigned long long v, float& x, float& y) {
    asm("mov.b64 {%0,%1}, %2;" : "=f"(x), "=f"(y) : "l"(v));
}

// ---------------- tiled GEMM body: out = A@W + bias (BM=32, BN=64, BK=32, 256 thr) ----------------
__device__ __forceinline__ void gemm_tile(const float* __restrict__ A, const float* __restrict__ W,
                                          const float* __restrict__ bias, float* __restrict__ out,
                                          int K, int Nc, int row0, int col0) {
    __shared__ __align__(16) float As[32][33];
    __shared__ __align__(16) float Ws[32][64];
    int t = threadIdx.x;
    int tx = t & 15, ty = t >> 4;
    int lm = t >> 3;
    int lk4 = t & 7;
    float acc[2][4] = {};
    for (int k0 = 0; k0 < K; k0 += 32) {
        float4 a4 = *reinterpret_cast<const float4*>(&A[(long)(row0 + lm) * K + k0 + lk4 * 4]);
        As[lk4 * 4 + 0][lm] = a4.x;
        As[lk4 * 4 + 1][lm] = a4.y;
        As[lk4 * 4 + 2][lm] = a4.z;
        As[lk4 * 4 + 3][lm] = a4.w;
        #pragma unroll
        for (int r = 0; r < 2; r++) {
            int li = t + 256 * r;
            int kk = li >> 4, c4 = li & 15;
            int col = col0 + c4 * 4;
            float4 w4 = make_float4(0.f, 0.f, 0.f, 0.f);
            if (col < Nc)
                w4 = *reinterpret_cast<const float4*>(&W[(long)(k0 + kk) * Nc + col]);
            *reinterpret_cast<float4*>(&Ws[kk][c4 * 4]) = w4;
        }
        __syncthreads();
        #pragma unroll
        for (int kk = 0; kk < 32; kk++) {
            float a0 = As[kk][ty * 2 + 0];
            float a1 = As[kk][ty * 2 + 1];
            float4 w = *reinterpret_cast<const float4*>(&Ws[kk][tx * 4]);
            acc[0][0] += a0 * w.x; acc[0][1] += a0 * w.y; acc[0][2] += a0 * w.z; acc[0][3] += a0 * w.w;
            acc[1][0] += a1 * w.x; acc[1][1] += a1 * w.y; acc[1][2] += a1 * w.z; acc[1][3] += a1 * w.w;
        }
        __syncthreads();
    }
    int col = col0 + tx * 4;
    if (col < Nc) {
        float4 b4 = *reinterpret_cast<const float4*>(&bias[col]);
        #pragma unroll
        for (int r = 0; r < 2; r++) {
            int row = row0 + ty * 2 + r;
            float4 o;
            o.x = acc[r][0] + b4.x; o.y = acc[r][1] + b4.y;
            o.z = acc[r][2] + b4.z; o.w = acc[r][3] + b4.w;
            *reinterpret_cast<float4*>(&out[(long)row * Nc + col]) = o;
        }
    }
}

__global__ void k_proj(const float* __restrict__ s,
                       const float* __restrict__ wq,  const float* __restrict__ bq,
                       const float* __restrict__ wkv, const float* __restrict__ bkv,
                       const float* __restrict__ wqp, const float* __restrict__ bqp,
                       const float* __restrict__ wkvp,const float* __restrict__ bkvp) {
    int bx = blockIdx.x;
    const float* W; const float* b; float* out; int Nc; int ct;
    if (bx < 3)       { W = wq;   b = bq;   out = g_qlin;   Nc = HC;       ct = bx; }
    else if (bx < 9)  { W = wkv;  b = bkv;  out = g_kvlin;  Nc = KV_COLS;  ct = bx - 3; }
    else if (bx < 12) { W = wqp;  b = bqp;  out = g_qplin;  Nc = QP_COLS;  ct = bx - 9; }
    else              { W = wkvp; b = bkvp; out = g_kvplin; Nc = KVP_COLS; ct = bx - 12; }
    gemm_tile(s, W, b, out, CN, Nc, blockIdx.y * 32, ct * 64);
}

__global__ void k_outgemm(const float* __restrict__ W, const float* __restrict__ bias,
                          float* __restrict__ out) {
    gemm_tile(g_cat, W, bias, out, CAT_DIM, CN, blockIdx.y * 32, blockIdx.x * 64);
}

// ---------------- point construction (merged) ----------------
__global__ void k_points_all(const float* __restrict__ rot, const float* __restrict__ trans) {
    int idx = blockIdx.x * 256 + threadIdx.x;
    if (idx >= N * 192) return;
    int i = idx / 192, p = idx % 192;
    float l0, l1, l2;
    if (p < 48) {
        const float* lin = g_qplin + i * QP_COLS;
        l0 = lin[p]; l1 = lin[48 + p]; l2 = lin[96 + p];
    } else {
        const float* lin = g_kvplin + i * KVP_COLS;
        int pp = p - 48;
        l0 = lin[pp]; l1 = lin[144 + pp]; l2 = lin[288 + pp];
    }
    const float* R = rot + i * 9;
    float o[3];
    #pragma unroll
    for (int d = 0; d < 3; d++)
        o[d] = R[d * 3 + 0] * l0 + R[d * 3 + 1] * l1 + R[d * 3 + 2] * l2 + trans[i * 3 + d];
    if (p < 48) {
        int h = p / PQ, tt = p % PQ;
        #pragma unroll
        for (int d = 0; d < 3; d++) g_qpts[i * 144 + h * 12 + tt * 3 + d] = o[d];
    } else {
        int pp = p - 48;
        int h = pp / 12, tt = pp % 12;
        if (tt < PQ) {
            #pragma unroll
            for (int d = 0; d < 3; d++) g_kpts[i * 144 + h * 12 + tt * 3 + d] = o[d];
        } else {
            #pragma unroll
            for (int d = 0; d < 3; d++) g_vpts[i * 288 + h * 24 + (tt - PQ) * 3 + d] = o[d];
        }
    }
}

// ---------------- z pass 1: bias GEMV, sync-free warp design ----------------
__global__ void __launch_bounds__(256) k_bias(const float* __restrict__ z,
                                              const float* __restrict__ wb,
                                              const float* __restrict__ bb) {
    __shared__ __align__(16) float wbT[12][128];
    __shared__ float bbs[12];
    int t = threadIdx.x;
    for (int idx = t; idx < 12 * 128; idx += 256) {
        int h = idx >> 7, c = idx & 127;
        wbT[h][c] = wb[c * 12 + h];
    }
    if (t < 12) bbs[t] = bb[t];
    __syncthreads();

    int w = t >> 5, l = t & 31;
    int jg = l & 7, cg = l >> 3;
    const float BS = 0.57735026918962576f; // sqrt(1/3)

    #pragma unroll
    for (int it = 0; it < 4; it++) {
        long row = (long)blockIdx.x * 256 + it * 64 + w * 8 + jg;
        const ulonglong2* zp = reinterpret_cast<const ulonglong2*>(z + row * 128);
        ulonglong2 zr[8];
        #pragma unroll
        for (int m = 0; m < 8; m++) zr[m] = zp[cg + 4 * m];   // coalesced per m, 8 in flight
        float accf[12];
        #pragma unroll
        for (int h = 0; h < 12; h++) {
            unsigned long long acc = 0ull;
            const ulonglong2* wp = reinterpret_cast<const ulonglong2*>(&wbT[h][0]);
            #pragma unroll
            for (int m = 0; m < 8; m++) {
                ulonglong2 ww = wp[cg + 4 * m];
                fma2(acc, zr[m].x, ww.x);
                fma2(acc, zr[m].y, ww.y);
            }
            accf[h] = hsum2(acc);
        }
        #pragma unroll
        for (int h = 0; h < 12; h++) {
            accf[h] += __shfl_xor_sync(0xffffffffu, accf[h], 8);
            accf[h] += __shfl_xor_sync(0xffffffffu, accf[h], 16);
        }
        if (cg == 0) {
            #pragma unroll
            for (int h = 0; h < 12; h++)
                g_logits[(long)h * NN + row] = BS * (accf[h] + bbs[h]);
        }
    }
}

// ---------------- qk + pt_att + mask: ADD into g_logits ----------------
__global__ void k_qk(const float* __restrict__ mask, const float* __restrict__ hwts) {
    __shared__ float qs[32][17], ks[32][17];
    __shared__ float qps[32][13], kps[32][13];
    int h = blockIdx.z;
    int i0 = blockIdx.y * 32, j0 = blockIdx.x * 32;
    int tx = threadIdx.x, ty = threadIdx.y;
    int tid = ty * 16 + tx;
    for (int r = 0; r < 2; r++) {
        int idx = tid + 256 * r;
        int ii = idx >> 4, c = idx & 15;
        qs[ii][c] = g_qlin[(i0 + ii) * HC + h * 16 + c];
        ks[ii][c] = g_kvlin[(j0 + ii) * KV_COLS + h * 32 + c];
        if (idx < 384) {
            int i2 = idx / 12, d = idx % 12;
            qps[i2][d] = g_qpts[(i0 + i2) * 144 + h * 12 + d];
            kps[i2][d] = g_kpts[(j0 + i2) * 144 + h * 12 + d];
        }
    }
    __syncthreads();
    float w = hwts[h];
    float hw = logf(1.0f + expf(w)) * 0.13608276348795434f; // softplus * sqrt(1/54)
    const float QK_SCALE = 0.14433756729740643f;            // sqrt(1/48)
    float dot[2][2] = {};
    float pt[2][2] = {};
    #pragma unroll
    for (int c = 0; c < 16; c++) {
        float a0 = qs[ty * 2][c], a1 = qs[ty * 2 + 1][c];
        float b0 = ks[tx * 2][c], b1 = ks[tx * 2 + 1][c];
        dot[0][0] += a0 * b0; dot[0][1] += a0 * b1;
        dot[1][0] += a1 * b0; dot[1][1] += a1 * b1;
    }
    #pragma unroll
    for (int d = 0; d < 12; d++) {
        float a0 = qps[ty * 2][d], a1 = qps[ty * 2 + 1][d];
        float b0 = kps[tx * 2][d], b1 = kps[tx * 2 + 1][d];
        float d00 = a0 - b0, d01 = a0 - b1, d10 = a1 - b0, d11 = a1 - b1;
        pt[0][0] += d00 * d00; pt[0][1] += d01 * d01;
        pt[1][0] += d10 * d10; pt[1][1] += d11 * d11;
    }
    #pragma unroll
    for (int a = 0; a < 2; a++) {
        int i = i0 + ty * 2 + a;
        #pragma unroll
        for (int b = 0; b < 2; b++) {
            int j = j0 + tx * 2 + b;
            float m = mask[i * N + j];
            float* L = &g_logits[(long)h * NN + i * N + j];
            *L += QK_SCALE * dot[a][b] - 0.5f * hw * pt[a][b] + INFV * (m - 1.0f);
        }
    }
}

// ---------------- softmax + o_pair (z re-read, MLP-4, warp j-slices + block reduce) ----------------
__global__ void __launch_bounds__(256) k_softmax_opair(const float* __restrict__ z) {
    extern __shared__ float sm[];
    float (*a_sh)[ASH_STRIDE] = reinterpret_cast<float(*)[ASH_STRIDE]>(sm + OP_ASH);
    float* rbuf = sm + OP_RED;   // [8 warps][6 heads][128 cols]

    int i = blockIdx.x;
    int t = threadIdx.x;

    // ---- stage logits ----
    #pragma unroll
    for (int r = 0; r < 36; r++) {
        int idx = t + 256 * r;
        int h = idx / 768, j = idx - h * 768;
        a_sh[h][j] = g_logits[(long)h * NN + i * N + j];
    }
    __syncthreads();

    // ---- softmax per head row (warp per row) ----
    int w = t >> 5, lane = t & 31;
    for (int h = w; h < 12; h += 8) {
        float m = -1e30f;
        #pragma unroll
        for (int e = 0; e < 24; e++) m = fmaxf(m, a_sh[h][lane + 32 * e]);
        #pragma unroll
        for (int off = 16; off; off >>= 1) m = fmaxf(m, __shfl_xor_sync(0xffffffffu, m, off));
        float sum = 0.f;
        #pragma unroll
        for (int e = 0; e < 24; e++) {
            float v = __expf(a_sh[h][lane + 32 * e] - m);
            a_sh[h][lane + 32 * e] = v;
            sum += v;
        }
        #pragma unroll
        for (int off = 16; off; off >>= 1) sum += __shfl_xor_sync(0xffffffffu, sum, off);
        float inv = 1.0f / sum;
        #pragma unroll
        for (int e = 0; e < 24; e++) a_sh[h][lane + 32 * e] *= inv;
    }
    __syncthreads();

    // ---- write normalized a back for k_av ----
    #pragma unroll
    for (int r = 0; r < 36; r++) {
        int idx = t + 256 * r;
        int h = idx / 768, j = idx - h * 768;
        g_logits[(long)h * NN + i * N + j] = a_sh[h][j];
    }

    // ---- o_pair: warp w owns j in [w*96, w*96+96), lane = column ull2 (4 floats) ----
    unsigned long long acc01[12] = {}, acc23[12] = {};
    const ulonglong2* zrow = reinterpret_cast<const ulonglong2*>(z + (long)i * N * CZ);
    for (int jj = 0; jj < 24; jj++) {
        int jb = w * 96 + jj * 4;
        ulonglong2 zz[4];
        #pragma unroll
        for (int k = 0; k < 4; k++) zz[k] = zrow[(jb + k) * 32 + lane];  // 4 coalesced LDGs in flight
        #pragma unroll
        for (int k = 0; k < 4; k++) {
            #pragma unroll
            for (int h = 0; h < 12; h++) {
                float av = a_sh[h][jb + k];
                unsigned long long aa = pk2(av, av);
                fma2(acc01[h], zz[k].x, aa);
                fma2(acc23[h], zz[k].y, aa);
            }
        }
    }

    // ---- block reduction across 8 warps, two rounds of 6 heads ----
    #pragma unroll
    for (int round = 0; round < 2; round++) {
        __syncthreads();   // protects rbuf reuse between rounds
        #pragma unroll
        for (int hh = 0; hh < 6; hh++) {
            int h = round * 6 + hh;
            float f0, f1, f2, f3;
            unpk2(acc01[h], f0, f1);
            unpk2(acc23[h], f2, f3);
            float4 v = make_float4(f0, f1, f2, f3);
            *reinterpret_cast<float4*>(&rbuf[(w * 6 + hh) * 128 + lane * 4]) = v;
        }
        __syncthreads();
        // 192 float4 outputs = 6 heads x 32 col-groups
        if (t < 192) {
            int hh = t >> 5, c4 = t & 31;
            float4 s = make_float4(0.f, 0.f, 0.f, 0.f);
            #pragma unroll
            for (int w2 = 0; w2 < 8; w2++) {
                float4 v = *reinterpret_cast<const float4*>(&rbuf[(w2 * 6 + hh) * 128 + c4 * 4]);
                s.x += v.x; s.y += v.y; s.z += v.z; s.w += v.w;
            }
            int h = round * 6 + hh;
            *reinterpret_cast<float4*>(&g_cat[(long)i * CAT_DIM + 576 + h * 128 + c4 * 4]) = s;
        }
    }
}

// ---------------- o = a@v, o_pt_global = a@v_pts ----------------
__global__ void k_av() {
    __shared__ float a_sh[32][64];
    __shared__ float vv_sh[64][41];
    int h = blockIdx.y;
    int i0 = blockIdx.x * 32;
    int tid = threadIdx.x;
    int i_local = tid >> 3;
    int cbase = tid & 7;
    float acc[5] = {};
    for (int j0 = 0; j0 < N; j0 += 64) {
        #pragma unroll
        for (int r = 0; r < 8; r++) {
            int idx = tid + 256 * r;
            int ii = idx >> 6, jj = idx & 63;
            a_sh[ii][jj] = g_logits[(long)h * NN + (i0 + ii) * N + j0 + jj];
        }
        #pragma unroll
        for (int r = 0; r < 10; r++) {
            int idx = tid + 256 * r;
            int jj = idx / 40, col = idx % 40;
            float val;
            if (col < 16) val = g_kvlin[(j0 + jj) * KV_COLS + h * 32 + 16 + col];
            else          val = g_vpts[(j0 + jj) * 288 + h * 24 + (col - 16)];
            vv_sh[jj][col] = val;
        }
        __syncthreads();
        #pragma unroll 4
        for (int jj = 0; jj < 64; jj++) {
            float av = a_sh[i_local][jj];
            #pragma unroll
            for (int k = 0; k < 5; k++) acc[k] += av * vv_sh[jj][cbase + 8 * k];
        }
        __syncthreads();
    }
    int i = i0 + i_local;
    #pragma unroll
    for (int k = 0; k < 5; k++) {
        int col = cbase + 8 * k;
        if (col < 16) g_cat[(long)i * CAT_DIM + h * 16 + col] = acc[k];
        else          g_optg[i * 288 + h * 24 + (col - 16)] = acc[k];
    }
}

// ---------------- o_pt: inverse frame + norm ----------------
__global__ void k_ptfinish(const float* __restrict__ rot, const float* __restrict__ trans) {
    int idx = blockIdx.x * 256 + threadIdx.x;
    if (idx >= N * H * PV) return;
    int i = idx / (H * PV);
    int hp = idx % (H * PV);
    int h = hp / PV, pv = hp % PV;
    float g[3];
    #pragma unroll
    for (int d = 0; d < 3; d++)
        g[d] = g_optg[i * 288 + h * 24 + pv * 3 + d] - trans[i * 3 + d];
    const float* R = rot + i * 9;
    float n2 = EPSV;
    #pragma unroll
    for (int jd = 0; jd < 3; jd++) {
        float loc = R[0 * 3 + jd] * g[0] + R[1 * 3 + jd] * g[1] + R[2 * 3 + jd] * g[2];
        g_cat[(long)i * CAT_DIM + 192 + 96 * jd + hp] = loc;
        n2 += loc * loc;
    }
    g_cat[(long)i * CAT_DIM + 480 + hp] = sqrtf(n2);
}

// ---------------- launch ----------------
extern "C" void kernel_launch(void* const* d_in, const int* in_sizes, int n_in,
                              void* d_out, int out_size) {
    const float* s     = (const float*)d_in[0];
    const float* z     = (const float*)d_in[1];
    const float* rot   = (const float*)d_in[2];
    const float* trans = (const float*)d_in[3];
    const float* mask  = (const float*)d_in[4];
    const float* wq    = (const float*)d_in[5];
    const float* bq    = (const float*)d_in[6];
    const float* wkv   = (const float*)d_in[7];
    const float* bkv   = (const float*)d_in[8];
    const float* wqp   = (const float*)d_in[9];
    const float* bqp   = (const float*)d_in[10];
    const float* wkvp  = (const float*)d_in[11];
    const float* bkvp  = (const float*)d_in[12];
    const float* wb    = (const float*)d_in[13];
    const float* bb    = (const float*)d_in[14];
    const float* hwts  = (const float*)d_in[15];
    const float* wout  = (const float*)d_in[16];
    const float* bout  = (const float*)d_in[17];
    float* out = (float*)d_out;

    cudaFuncSetAttribute(k_softmax_opair, cudaFuncAttributeMaxDynamicSharedMemorySize, OP_SMEM_BYTES);

    // z pass 1 (independent of projections): bias -> g_logits
    k_bias<<<NN / 256, 256>>>(z, wb, bb);
    // projections + points
    k_proj<<<dim3(19, 24), 256>>>(s, wq, bq, wkv, bkv, wqp, bqp, wkvp, bkvp);
    k_points_all<<<(N * 192 + 255) / 256, 256>>>(rot, trans);
    // qk + pt + mask terms += g_logits
    k_qk<<<dim3(N / 32, N / 32, H), dim3(16, 16)>>>(mask, hwts);
    // softmax + o_pair (z pass 2)
    k_softmax_opair<<<N, 256, OP_SMEM_BYTES>>>(z);
    // a @ [v, v_pts]
    k_av<<<dim3(N / 32, H), 256>>>();
    // invert frames + norms
    k_ptfinish<<<(N * H * PV + 255) / 256, 256>>>(rot, trans);
    // output projection
    k_outgemm<<<dim3(6, 24), 256>>>(wout, bout, out);
}

// round 7
// speedup vs baseline: 1.3108x; 1.3108x over previous
#include <cuda_runtime.h>
#include <math.h>

#define N    768
#define CN   384
#define CZ   128
#define CC   16
#define H    12
#define PQ   4
#define PV   8
#define NN   (N*N)                 // 589824
#define HC   (H*CC)                // 192
#define KV_COLS (2*HC)             // 384
#define QP_COLS (H*PQ*3)           // 144
#define KVP_COLS (H*12*3)          // 432
#define CAT_DIM (H*(CZ+CC+PV*4))   // 2112
#define INFV 100000.0f
#define EPSV 1e-8f

// ---------------- scratch ----------------
__device__ float g_qlin  [N*HC];
__device__ float g_kvlin [N*KV_COLS];
__device__ float g_qplin [N*QP_COLS];
__device__ float g_kvplin[N*KVP_COLS];
__device__ float g_qpts  [N*H*PQ*3];
__device__ float g_kpts  [N*H*PQ*3];
__device__ float g_vpts  [N*H*PV*3];
__device__ float g_logits[H*NN];        // 28 MB: logits, then softmaxed a
__device__ float g_optg  [N*H*PV*3];
__device__ float g_cat   [N*CAT_DIM];

// ---------------- f32x2 packed-FMA helpers ----------------
__device__ __forceinline__ void fma2(unsigned long long& acc, unsigned long long a, unsigned long long b) {
    asm("fma.rn.f32x2 %0, %1, %2, %0;" : "+l"(acc) : "l"(a), "l"(b));
}
__device__ __forceinline__ unsigned long long pk2(float a, float b) {
    unsigned long long r; asm("mov.b64 %0, {%1,%2};" : "=l"(r) : "f"(a), "f"(b)); return r;
}
__device__ __forceinline__ float hsum2(unsigned long long v) {
    float x, y; asm("mov.b64 {%0,%1}, %2;" : "=f"(x), "=f"(y) : "l"(v)); return x + y;
}

// ---------------- tiled GEMM body: out = A@W + bias (BM=32, BN=64, BK=32, 256 thr) ----------------
__device__ __forceinline__ void gemm_tile(const float* __restrict__ A, const float* __restrict__ W,
                                          const float* __restrict__ bias, float* __restrict__ out,
                                          int K, int Nc, int row0, int col0) {
    __shared__ __align__(16) float As[32][33];
    __shared__ __align__(16) float Ws[32][64];
    int t = threadIdx.x;
    int tx = t & 15, ty = t >> 4;
    int lm = t >> 3;
    int lk4 = t & 7;
    float acc[2][4] = {};
    for (int k0 = 0; k0 < K; k0 += 32) {
        float4 a4 = *reinterpret_cast<const float4*>(&A[(long)(row0 + lm) * K + k0 + lk4 * 4]);
        As[lk4 * 4 + 0][lm] = a4.x;
        As[lk4 * 4 + 1][lm] = a4.y;
        As[lk4 * 4 + 2][lm] = a4.z;
        As[lk4 * 4 + 3][lm] = a4.w;
        #pragma unroll
        for (int r = 0; r < 2; r++) {
            int li = t + 256 * r;
            int kk = li >> 4, c4 = li & 15;
            int col = col0 + c4 * 4;
            float4 w4 = make_float4(0.f, 0.f, 0.f, 0.f);
            if (col < Nc)
                w4 = *reinterpret_cast<const float4*>(&W[(long)(k0 + kk) * Nc + col]);
            *reinterpret_cast<float4*>(&Ws[kk][c4 * 4]) = w4;
        }
        __syncthreads();
        #pragma unroll
        for (int kk = 0; kk < 32; kk++) {
            float a0 = As[kk][ty * 2 + 0];
            float a1 = As[kk][ty * 2 + 1];
            float4 w = *reinterpret_cast<const float4*>(&Ws[kk][tx * 4]);
            acc[0][0] += a0 * w.x; acc[0][1] += a0 * w.y; acc[0][2] += a0 * w.z; acc[0][3] += a0 * w.w;
            acc[1][0] += a1 * w.x; acc[1][1] += a1 * w.y; acc[1][2] += a1 * w.z; acc[1][3] += a1 * w.w;
        }
        __syncthreads();
    }
    int col = col0 + tx * 4;
    if (col < Nc) {
        float4 b4 = *reinterpret_cast<const float4*>(&bias[col]);
        #pragma unroll
        for (int r = 0; r < 2; r++) {
            int row = row0 + ty * 2 + r;
            float4 o;
            o.x = acc[r][0] + b4.x; o.y = acc[r][1] + b4.y;
            o.z = acc[r][2] + b4.z; o.w = acc[r][3] + b4.w;
            *reinterpret_cast<float4*>(&out[(long)row * Nc + col]) = o;
        }
    }
}

__global__ void k_proj(const float* __restrict__ s,
                       const float* __restrict__ wq,  const float* __restrict__ bq,
                       const float* __restrict__ wkv, const float* __restrict__ bkv,
                       const float* __restrict__ wqp, const float* __restrict__ bqp,
                       const float* __restrict__ wkvp,const float* __restrict__ bkvp) {
    int bx = blockIdx.x;
    const float* W; const float* b; float* out; int Nc; int ct;
    if (bx < 3)       { W = wq;   b = bq;   out = g_qlin;   Nc = HC;       ct = bx; }
    else if (bx < 9)  { W = wkv;  b = bkv;  out = g_kvlin;  Nc = KV_COLS;  ct = bx - 3; }
    else if (bx < 12) { W = wqp;  b = bqp;  out = g_qplin;  Nc = QP_COLS;  ct = bx - 9; }
    else              { W = wkvp; b = bkvp; out = g_kvplin; Nc = KVP_COLS; ct = bx - 12; }
    gemm_tile(s, W, b, out, CN, Nc, blockIdx.y * 32, ct * 64);
}

__global__ void k_outgemm(const float* __restrict__ W, const float* __restrict__ bias,
                          float* __restrict__ out) {
    gemm_tile(g_cat, W, bias, out, CAT_DIM, CN, blockIdx.y * 32, blockIdx.x * 64);
}

// ---------------- point construction (merged) ----------------
__global__ void k_points_all(const float* __restrict__ rot, const float* __restrict__ trans) {
    int idx = blockIdx.x * 256 + threadIdx.x;
    if (idx >= N * 192) return;
    int i = idx / 192, p = idx % 192;
    float l0, l1, l2;
    if (p < 48) {
        const float* lin = g_qplin + i * QP_COLS;
        l0 = lin[p]; l1 = lin[48 + p]; l2 = lin[96 + p];
    } else {
        const float* lin = g_kvplin + i * KVP_COLS;
        int pp = p - 48;
        l0 = lin[pp]; l1 = lin[144 + pp]; l2 = lin[288 + pp];
    }
    const float* R = rot + i * 9;
    float o[3];
    #pragma unroll
    for (int d = 0; d < 3; d++)
        o[d] = R[d * 3 + 0] * l0 + R[d * 3 + 1] * l1 + R[d * 3 + 2] * l2 + trans[i * 3 + d];
    if (p < 48) {
        int h = p / PQ, tt = p % PQ;
        #pragma unroll
        for (int d = 0; d < 3; d++) g_qpts[i * 144 + h * 12 + tt * 3 + d] = o[d];
    } else {
        int pp = p - 48;
        int h = pp / 12, tt = pp % 12;
        if (tt < PQ) {
            #pragma unroll
            for (int d = 0; d < 3; d++) g_kpts[i * 144 + h * 12 + tt * 3 + d] = o[d];
        } else {
            #pragma unroll
            for (int d = 0; d < 3; d++) g_vpts[i * 288 + h * 24 + (tt - PQ) * 3 + d] = o[d];
        }
    }
}

// ---------------- z pass 1: smem-staged bias GEMV, 2 rows/thread (weight-LDS amortized) ----------------
__global__ void __launch_bounds__(128) k_bias(const float* __restrict__ z,
                                              const float* __restrict__ wb,
                                              const float* __restrict__ bb) {
    __shared__ __align__(16) float wbT[12][128];
    __shared__ float bbs[12];
    __shared__ __align__(16) float s_z[256][36];   // 32 cols + pad4
    int t = threadIdx.x;
    for (int idx = t; idx < 12 * 128; idx += 128) {
        int h = idx >> 7, c = idx & 127;
        wbT[h][c] = wb[c * 12 + h];
    }
    if (t < 12) bbs[t] = bb[t];
    long ij0 = (long)blockIdx.x * 256;
    unsigned long long accA[12] = {}, accB[12] = {};
    #pragma unroll
    for (int cc = 0; cc < 4; cc++) {
        __syncthreads();
        #pragma unroll
        for (int r = 0; r < 16; r++) {
            int idx = t + 128 * r;            // < 2048
            int row = idx >> 3, c4 = idx & 7;
            float4 v = *reinterpret_cast<const float4*>(&z[(ij0 + row) * 128 + cc * 32 + c4 * 4]);
            *reinterpret_cast<float4*>(&s_z[row][c4 * 4]) = v;
        }
        __syncthreads();
        #pragma unroll
        for (int c4 = 0; c4 < 8; c4++) {
            ulonglong2 za = *reinterpret_cast<const ulonglong2*>(&s_z[t][c4 * 4]);
            ulonglong2 zb = *reinterpret_cast<const ulonglong2*>(&s_z[t + 128][c4 * 4]);
            #pragma unroll
            for (int h = 0; h < 12; h++) {
                ulonglong2 ww = *reinterpret_cast<const ulonglong2*>(&wbT[h][cc * 32 + c4 * 4]);
                fma2(accA[h], za.x, ww.x);
                fma2(accA[h], za.y, ww.y);
                fma2(accB[h], zb.x, ww.x);
                fma2(accB[h], zb.y, ww.y);
            }
        }
    }
    const float BS = 0.57735026918962576f; // sqrt(1/3)
    #pragma unroll
    for (int h = 0; h < 12; h++) {
        g_logits[(long)h * NN + ij0 + t]       = BS * (hsum2(accA[h]) + bbs[h]);
        g_logits[(long)h * NN + ij0 + 128 + t] = BS * (hsum2(accB[h]) + bbs[h]);
    }
}

// ---------------- logits += qk + pt_att + mask ----------------
__global__ void k_qk(const float* __restrict__ mask, const float* __restrict__ hwts) {
    __shared__ float qs[32][17], ks[32][17];
    __shared__ float qps[32][13], kps[32][13];
    int h = blockIdx.z;
    int i0 = blockIdx.y * 32, j0 = blockIdx.x * 32;
    int tx = threadIdx.x, ty = threadIdx.y;
    int tid = ty * 16 + tx;
    for (int r = 0; r < 2; r++) {
        int idx = tid + 256 * r;
        int ii = idx >> 4, c = idx & 15;
        qs[ii][c] = g_qlin[(i0 + ii) * HC + h * 16 + c];
        ks[ii][c] = g_kvlin[(j0 + ii) * KV_COLS + h * 32 + c];
        if (idx < 384) {
            int i2 = idx / 12, d = idx % 12;
            qps[i2][d] = g_qpts[(i0 + i2) * 144 + h * 12 + d];
            kps[i2][d] = g_kpts[(j0 + i2) * 144 + h * 12 + d];
        }
    }
    __syncthreads();
    float w = hwts[h];
    float hw = logf(1.0f + expf(w)) * 0.13608276348795434f; // softplus * sqrt(1/54)
    const float QK_SCALE = 0.14433756729740643f;            // sqrt(1/48)
    float dot[2][2] = {};
    float pt[2][2] = {};
    #pragma unroll
    for (int c = 0; c < 16; c++) {
        float a0 = qs[ty * 2][c], a1 = qs[ty * 2 + 1][c];
        float b0 = ks[tx * 2][c], b1 = ks[tx * 2 + 1][c];
        dot[0][0] += a0 * b0; dot[0][1] += a0 * b1;
        dot[1][0] += a1 * b0; dot[1][1] += a1 * b1;
    }
    #pragma unroll
    for (int d = 0; d < 12; d++) {
        float a0 = qps[ty * 2][d], a1 = qps[ty * 2 + 1][d];
        float b0 = kps[tx * 2][d], b1 = kps[tx * 2 + 1][d];
        float d00 = a0 - b0, d01 = a0 - b1, d10 = a1 - b0, d11 = a1 - b1;
        pt[0][0] += d00 * d00; pt[0][1] += d01 * d01;
        pt[1][0] += d10 * d10; pt[1][1] += d11 * d11;
    }
    #pragma unroll
    for (int a = 0; a < 2; a++) {
        int i = i0 + ty * 2 + a;
        #pragma unroll
        for (int b = 0; b < 2; b++) {
            int j = j0 + tx * 2 + b;
            float m = mask[i * N + j];
            float* L = &g_logits[(long)h * NN + i * N + j];
            *L += QK_SCALE * dot[a][b] - 0.5f * hw * pt[a][b] + INFV * (m - 1.0f);
        }
    }
}

// ---------------- z pass 2 fused with softmax: a = softmax(logits); o_pair = a @ z ----------------
__global__ void __launch_bounds__(256, 2) k_opair(const float* __restrict__ z) {
    __shared__ float a_sh[12][768];   // 36 KB
    int i = blockIdx.x;
    int t = threadIdx.x;
    // stage all 12 logits rows for residue i
    #pragma unroll
    for (int r = 0; r < 36; r++) {
        int idx = t + 256 * r;
        int h = idx / 768, j = idx - h * 768;
        a_sh[h][j] = g_logits[(long)h * NN + i * N + j];
    }
    __syncthreads();
    // softmax per head row (warp per row, shfl-only)
    int w = t >> 5, lane = t & 31;
    for (int h = w; h < 12; h += 8) {
        float m = -1e30f;
        #pragma unroll
        for (int e = 0; e < 24; e++) m = fmaxf(m, a_sh[h][lane + 32 * e]);
        #pragma unroll
        for (int off = 16; off; off >>= 1) m = fmaxf(m, __shfl_xor_sync(0xffffffffu, m, off));
        float sum = 0.f;
        #pragma unroll
        for (int e = 0; e < 24; e++) {
            float v = __expf(a_sh[h][lane + 32 * e] - m);
            a_sh[h][lane + 32 * e] = v;
            sum += v;
        }
        #pragma unroll
        for (int off = 16; off; off >>= 1) sum += __shfl_xor_sync(0xffffffffu, sum, off);
        float inv = 1.0f / sum;
        #pragma unroll
        for (int e = 0; e < 24; e++) a_sh[h][lane + 32 * e] *= inv;
    }
    __syncthreads();
    // write normalized a back for k_av (coalesced)
    #pragma unroll
    for (int r = 0; r < 36; r++) {
        int idx = t + 256 * r;
        int h = idx / 768, j = idx - h * 768;
        g_logits[(long)h * NN + i * N + j] = a_sh[h][j];
    }
    // o_pair: c4 = column float4 (32 total), g = j-interleave group within warp (8)
    int c4 = (t >> 5) * 4 + ((t & 31) >> 3);   // 0..31
    int g = t & 7;                             // 0..7
    unsigned long long acc01[12] = {}, acc23[12] = {};
    const ulonglong2* zrow = reinterpret_cast<const ulonglong2*>(z + (long)i * N * CZ);
    for (int jo = 0; jo < 24; jo++) {
        ulonglong2 zz[4];
        #pragma unroll
        for (int k = 0; k < 4; k++) {
            int j = (jo * 4 + k) * 8 + g;
            zz[k] = zrow[j * 32 + c4];          // 4 loads in flight
        }
        #pragma unroll
        for (int k = 0; k < 4; k++) {
            int j = (jo * 4 + k) * 8 + g;
            #pragma unroll
            for (int h = 0; h < 12; h++) {
                float av = a_sh[h][j];
                unsigned long long aa = pk2(av, av);
                fma2(acc01[h], zz[k].x, aa);
                fma2(acc23[h], zz[k].y, aa);
            }
        }
    }
    // reduce over g (8 lanes within each 8-lane chunk of the warp)
    #pragma unroll
    for (int h = 0; h < 12; h++) {
        float s0, s1, s2, s3;
        { float x, y; asm("mov.b64 {%0,%1}, %2;" : "=f"(x), "=f"(y) : "l"(acc01[h])); s0 = x; s1 = y; }
        { float x, y; asm("mov.b64 {%0,%1}, %2;" : "=f"(x), "=f"(y) : "l"(acc23[h])); s2 = x; s3 = y; }
        #pragma unroll
        for (int off = 4; off; off >>= 1) {
            s0 += __shfl_xor_sync(0xffffffffu, s0, off);
            s1 += __shfl_xor_sync(0xffffffffu, s1, off);
            s2 += __shfl_xor_sync(0xffffffffu, s2, off);
            s3 += __shfl_xor_sync(0xffffffffu, s3, off);
        }
        if (g == 0) {
            float* dst = &g_cat[(long)i * CAT_DIM + 576 + h * 128 + c4 * 4];
            dst[0] = s0; dst[1] = s1; dst[2] = s2; dst[3] = s3;
        }
    }
}

// ---------------- o = a@v, o_pt_global = a@v_pts ----------------
__global__ void k_av() {
    __shared__ float a_sh[32][64];
    __shared__ float vv_sh[64][41];
    int h = blockIdx.y;
    int i0 = blockIdx.x * 32;
    int tid = threadIdx.x;
    int i_local = tid >> 3;
    int cbase = tid & 7;
    float acc[5] = {};
    for (int j0 = 0; j0 < N; j0 += 64) {
        #pragma unroll
        for (int r = 0; r < 8; r++) {
            int idx = tid + 256 * r;
            int ii = idx >> 6, jj = idx & 63;
            a_sh[ii][jj] = g_logits[(long)h * NN + (i0 + ii) * N + j0 + jj];
        }
        #pragma unroll
        for (int r = 0; r < 10; r++) {
            int idx = tid + 256 * r;
            int jj = idx / 40, col = idx % 40;
            float val;
            if (col < 16) val = g_kvlin[(j0 + jj) * KV_COLS + h * 32 + 16 + col];
            else          val = g_vpts[(j0 + jj) * 288 + h * 24 + (col - 16)];
            vv_sh[jj][col] = val;
        }
        __syncthreads();
        #pragma unroll 4
        for (int jj = 0; jj < 64; jj++) {
            float av = a_sh[i_local][jj];
            #pragma unroll
            for (int k = 0; k < 5; k++) acc[k] += av * vv_sh[jj][cbase + 8 * k];
        }
        __syncthreads();
    }
    int i = i0 + i_local;
    #pragma unroll
    for (int k = 0; k < 5; k++) {
        int col = cbase + 8 * k;
        if (col < 16) g_cat[(long)i * CAT_DIM + h * 16 + col] = acc[k];
        else          g_optg[i * 288 + h * 24 + (col - 16)] = acc[k];
    }
}

// ---------------- o_pt: inverse frame + norm ----------------
__global__ void k_ptfinish(const float* __restrict__ rot, const float* __restrict__ trans) {
    int idx = blockIdx.x * 256 + threadIdx.x;
    if (idx >= N * H * PV) return;
    int i = idx / (H * PV);
    int hp = idx % (H * PV);
    int h = hp / PV, pv = hp % PV;
    float g[3];
    #pragma unroll
    for (int d = 0; d < 3; d++)
        g[d] = g_optg[i * 288 + h * 24 + pv * 3 + d] - trans[i * 3 + d];
    const float* R = rot + i * 9;
    float n2 = EPSV;
    #pragma unroll
    for (int jd = 0; jd < 3; jd++) {
        float loc = R[0 * 3 + jd] * g[0] + R[1 * 3 + jd] * g[1] + R[2 * 3 + jd] * g[2];
        g_cat[(long)i * CAT_DIM + 192 + 96 * jd + hp] = loc;
        n2 += loc * loc;
    }
    g_cat[(long)i * CAT_DIM + 480 + hp] = sqrtf(n2);
}

// ---------------- launch ----------------
extern "C" void kernel_launch(void* const* d_in, const int* in_sizes, int n_in,
                              void* d_out, int out_size) {
    const float* s     = (const float*)d_in[0];
    const float* z     = (const float*)d_in[1];
    const float* rot   = (const float*)d_in[2];
    const float* trans = (const float*)d_in[3];
    const float* mask  = (const float*)d_in[4];
    const float* wq    = (const float*)d_in[5];
    const float* bq    = (const float*)d_in[6];
    const float* wkv   = (const float*)d_in[7];
    const float* bkv   = (const float*)d_in[8];
    const float* wqp   = (const float*)d_in[9];
    const float* bqp   = (const float*)d_in[10];
    const float* wkvp  = (const float*)d_in[11];
    const float* bkvp  = (const float*)d_in[12];
    const float* wb    = (const float*)d_in[13];
    const float* bb    = (const float*)d_in[14];
    const float* hwts  = (const float*)d_in[15];
    const float* wout  = (const float*)d_in[16];
    const float* bout  = (const float*)d_in[17];
    float* out = (float*)d_out;

    // projections + points
    k_proj<<<dim3(19, 24), 256>>>(s, wq, bq, wkv, bkv, wqp, bqp, wkvp, bkvp);
    k_points_all<<<(N * 192 + 255) / 256, 256>>>(rot, trans);
    // z pass 1: pair bias -> logits
    k_bias<<<NN / 256, 128>>>(z, wb, bb);
    // scalar + point attention + mask (+=)
    k_qk<<<dim3(N / 32, N / 32, H), dim3(16, 16)>>>(mask, hwts);
    // softmax + z pass 2 (o_pair) fused; writes normalized a back
    k_opair<<<N, 256>>>(z);
    // a @ [v, v_pts]
    k_av<<<dim3(N / 32, H), 256>>>();
    // invert frames + norms
    k_ptfinish<<<(N * H * PV + 255) / 256, 256>>>(rot, trans);
    // output projection
    k_outgemm<<<dim3(6, 24), 256>>>(wout, bout, out);
}